// round 4
// baseline (speedup 1.0000x reference)
#include <cuda_runtime.h>
#include <math.h>
#include <stdint.h>

#define BB 4
#define NTOK 2048
#define DMODEL 1024
#define NH 16
#define DH 64
#define MROWS (BB * NTOK)            // 8192
#define QKVCOLS (3 * DMODEL)         // 3072

// Scratch (no allocations allowed)
__device__ float g_qkv[(size_t)MROWS * QKVCOLS];   // 96 MB
__device__ float g_att[(size_t)MROWS * DMODEL];    // 32 MB

__device__ __forceinline__ uint32_t f2tf32(float x) {
    uint32_t u;
    asm volatile("cvt.rna.tf32.f32 %0, %1;" : "=r"(u) : "f"(x));
    return u;
}

// ---------------------------------------------------------------------------
// TF32 tensor-core GEMM, 2-stage smem pipeline.
// C[M,N] = A[M,K] @ B[K,N] + bias[N]
// 128x128 CTA tile, BK=32, 256 threads (8 warps, 64x32 warp tile).
// One __syncthreads per K-iter; STS of next stage overlaps mma of current.
// ---------------------------------------------------------------------------
#define BK 32
#define APAD 36
#define BPAD 132
#define ASTRIDE (128 * APAD)
#define BSTRIDE (BK * BPAD)

__global__ __launch_bounds__(256, 2) void gemm_tf32_bias(
    const float* __restrict__ A,
    const float* __restrict__ B,
    const float* __restrict__ bias,
    float* __restrict__ C,
    int M, int N, int K)
{
    extern __shared__ uint32_t smem_g[];
    uint32_t* As = smem_g;                    // 2 stages of 128*APAD
    uint32_t* Bs = smem_g + 2 * ASTRIDE;      // 2 stages of BK*BPAD

    const int tid  = threadIdx.x;
    const int lane = tid & 31;
    const int wid  = tid >> 5;
    const int row0 = blockIdx.y * 128;
    const int col0 = blockIdx.x * 128;

    const int wm0 = (wid >> 2) * 64;
    const int wn0 = (wid & 3) * 32;
    const int gr  = lane >> 2;
    const int gc  = lane & 3;

    const int arow = tid >> 3;
    const int acol = (tid & 7) * 4;
    const int brow = tid >> 5;
    const int bcol = (tid & 31) * 4;

    float4 aReg[4], bReg[4];
    const int niter = K / BK;

    // prefetch tile 0 and stage into buffer 0
    #pragma unroll
    for (int p = 0; p < 4; p++) {
        aReg[p] = *(const float4*)&A[(size_t)(row0 + arow + p * 32) * K + acol];
        bReg[p] = *(const float4*)&B[(size_t)(brow + p * 8) * N + col0 + bcol];
    }
    #pragma unroll
    for (int p = 0; p < 4; p++) {
        uint32_t* as = &As[(arow + p * 32) * APAD + acol];
        as[0] = f2tf32(aReg[p].x); as[1] = f2tf32(aReg[p].y);
        as[2] = f2tf32(aReg[p].z); as[3] = f2tf32(aReg[p].w);
        uint32_t* bs = &Bs[(brow + p * 8) * BPAD + bcol];
        bs[0] = f2tf32(bReg[p].x); bs[1] = f2tf32(bReg[p].y);
        bs[2] = f2tf32(bReg[p].z); bs[3] = f2tf32(bReg[p].w);
    }

    float acc[4][4][4];
    #pragma unroll
    for (int i = 0; i < 4; i++)
        #pragma unroll
        for (int j = 0; j < 4; j++)
            #pragma unroll
            for (int q = 0; q < 4; q++) acc[i][j][q] = 0.f;

    for (int it = 0; it < niter; it++) {
        __syncthreads();   // stage (it&1) stores visible; prev readers of (it^1)&1 done
        const uint32_t* Ab = As + (it & 1) * ASTRIDE;
        const uint32_t* Bb = Bs + (it & 1) * BSTRIDE;

        // prefetch next tile from gmem (overlaps compute below)
        if (it + 1 < niter) {
            int k0 = (it + 1) * BK;
            #pragma unroll
            for (int p = 0; p < 4; p++) {
                aReg[p] = *(const float4*)&A[(size_t)(row0 + arow + p * 32) * K + k0 + acol];
                bReg[p] = *(const float4*)&B[(size_t)(k0 + brow + p * 8) * N + col0 + bcol];
            }
        }

        #pragma unroll
        for (int kk = 0; kk < 4; kk++) {
            const int kb = kk * 8;
            uint32_t af[4][4], bf[4][2];
            #pragma unroll
            for (int mt = 0; mt < 4; mt++) {
                const uint32_t* base = &Ab[(wm0 + mt * 16 + gr) * APAD + kb + gc];
                af[mt][0] = base[0];
                af[mt][1] = base[8 * APAD];
                af[mt][2] = base[4];
                af[mt][3] = base[8 * APAD + 4];
            }
            #pragma unroll
            for (int nt = 0; nt < 4; nt++) {
                const uint32_t* base = &Bb[(kb + gc) * BPAD + wn0 + nt * 8 + gr];
                bf[nt][0] = base[0];
                bf[nt][1] = base[4 * BPAD];
            }
            #pragma unroll
            for (int mt = 0; mt < 4; mt++)
                #pragma unroll
                for (int nt = 0; nt < 4; nt++) {
                    asm volatile(
                        "mma.sync.aligned.m16n8k8.row.col.f32.tf32.tf32.f32 "
                        "{%0,%1,%2,%3}, {%4,%5,%6,%7}, {%8,%9}, {%0,%1,%2,%3};"
                        : "+f"(acc[mt][nt][0]), "+f"(acc[mt][nt][1]),
                          "+f"(acc[mt][nt][2]), "+f"(acc[mt][nt][3])
                        : "r"(af[mt][0]), "r"(af[mt][1]), "r"(af[mt][2]), "r"(af[mt][3]),
                          "r"(bf[nt][0]), "r"(bf[nt][1]));
                }
        }

        // stage next tile into the other buffer (no barrier needed: its previous
        // readers finished before the sync at the top of this iteration)
        if (it + 1 < niter) {
            uint32_t* Aw = As + ((it + 1) & 1) * ASTRIDE;
            uint32_t* Bw = Bs + ((it + 1) & 1) * BSTRIDE;
            #pragma unroll
            for (int p = 0; p < 4; p++) {
                uint32_t* as = &Aw[(arow + p * 32) * APAD + acol];
                as[0] = f2tf32(aReg[p].x); as[1] = f2tf32(aReg[p].y);
                as[2] = f2tf32(aReg[p].z); as[3] = f2tf32(aReg[p].w);
                uint32_t* bs = &Bw[(brow + p * 8) * BPAD + bcol];
                bs[0] = f2tf32(bReg[p].x); bs[1] = f2tf32(bReg[p].y);
                bs[2] = f2tf32(bReg[p].z); bs[3] = f2tf32(bReg[p].w);
            }
        }
    }

    #pragma unroll
    for (int mt = 0; mt < 4; mt++) {
        int r = row0 + wm0 + mt * 16 + gr;
        #pragma unroll
        for (int nt = 0; nt < 4; nt++) {
            int c = col0 + wn0 + nt * 8 + 2 * gc;
            float bv0 = bias[c], bv1 = bias[c + 1];
            C[(size_t)r * N + c]           = acc[mt][nt][0] + bv0;
            C[(size_t)r * N + c + 1]       = acc[mt][nt][1] + bv1;
            C[(size_t)(r + 8) * N + c]     = acc[mt][nt][2] + bv0;
            C[(size_t)(r + 8) * N + c + 1] = acc[mt][nt][3] + bv1;
        }
    }
}

// ---------------------------------------------------------------------------
// TF32 tensor-core causal flash attention with K/V register prefetch.
// CTA = (b, h, 128-query-row tile). 256 threads = 8 warps; warp owns 16 q-rows.
// ---------------------------------------------------------------------------
#define QT 128
#define KT 64
#define QPAD 68

__global__ __launch_bounds__(256, 2) void attn_tf32(
    const float* __restrict__ qkv, float* __restrict__ out)
{
    extern __shared__ uint32_t sm_u[];
    uint32_t* Qs = sm_u;                       // 128*68
    uint32_t* Ks = Qs + QT * QPAD;             // 64*68
    uint32_t* Vs = Ks + KT * QPAD;             // 64*68
    uint32_t* Ps = Vs + KT * QPAD;             // 128*68

    const int tid  = threadIdx.x;
    const int lane = tid & 31;
    const int wid  = tid >> 5;
    const int gr   = lane >> 2;
    const int gc   = lane & 3;

    const int bh = blockIdx.x;
    const int b  = bh >> 4;
    const int h  = bh & 15;
    const int qi = (gridDim.y - 1) - blockIdx.y;   // heavy tiles first
    const int q0 = qi * QT;
    const float scale = 0.125f;

    // per-thread KV load coordinates (float4 over 64x16 float4-grid)
    const int kvr = tid >> 4;              // 0..15 (+p*16)... see loop mapping
    (void)kvr;

    // ---- load Q tile [128 x 64] -> tf32 smem ----
    {
        const size_t qbase = (size_t)(b * NTOK + q0) * QKVCOLS + h * DH;
        #pragma unroll
        for (int p = 0; p < 8; p++) {
            int idx = tid + p * 256;
            int r = idx >> 4, c = (idx & 15) * 4;
            float4 v = *(const float4*)&qkv[qbase + (size_t)r * QKVCOLS + c];
            uint32_t* d = &Qs[r * QPAD + c];
            d[0] = f2tf32(v.x); d[1] = f2tf32(v.y);
            d[2] = f2tf32(v.z); d[3] = f2tf32(v.w);
        }
    }

    const size_t kvbase = (size_t)(b * NTOK) * QKVCOLS + DMODEL + h * DH;
    const int nkv = 2 * qi + 2;
    const int wrow0 = q0 + wid * 16;

    float4 kpre[4], vpre[4];
    // prologue: fetch KV tile 0 into regs, stage to smem
    #pragma unroll
    for (int p = 0; p < 4; p++) {
        int idx = tid + p * 256;
        int r = idx >> 4, c = (idx & 15) * 4;
        size_t off = kvbase + (size_t)r * QKVCOLS + c;
        kpre[p] = *(const float4*)&qkv[off];
        vpre[p] = *(const float4*)&qkv[off + DMODEL];
    }
    #pragma unroll
    for (int p = 0; p < 4; p++) {
        int idx = tid + p * 256;
        int r = idx >> 4, c = (idx & 15) * 4;
        uint32_t* dk = &Ks[r * QPAD + c];
        dk[0] = f2tf32(kpre[p].x); dk[1] = f2tf32(kpre[p].y);
        dk[2] = f2tf32(kpre[p].z); dk[3] = f2tf32(kpre[p].w);
        uint32_t* dv = &Vs[r * QPAD + c];
        dv[0] = f2tf32(vpre[p].x); dv[1] = f2tf32(vpre[p].y);
        dv[2] = f2tf32(vpre[p].z); dv[3] = f2tf32(vpre[p].w);
    }

    float accO[8][4];
    #pragma unroll
    for (int nt = 0; nt < 8; nt++)
        #pragma unroll
        for (int q = 0; q < 4; q++) accO[nt][q] = 0.f;
    float mrow[2] = { -INFINITY, -INFINITY };
    float lrow[2] = { 0.f, 0.f };

    __syncthreads();   // Qs + KV tile 0 visible

    for (int j = 0; j < nkv; j++) {
        // prefetch next KV tile into regs (overlaps all compute below)
        if (j + 1 < nkv) {
            #pragma unroll
            for (int p = 0; p < 4; p++) {
                int idx = tid + p * 256;
                int r = idx >> 4, c = (idx & 15) * 4;
                size_t off = kvbase + (size_t)((j + 1) * KT + r) * QKVCOLS + c;
                kpre[p] = *(const float4*)&qkv[off];
                vpre[p] = *(const float4*)&qkv[off + DMODEL];
            }
        }

        if (j * KT <= wrow0 + 15) {          // warp has unmasked work
            // ---- S = Q @ K^T (16 x 64 per warp) ----
            float s[8][4];
            #pragma unroll
            for (int nt = 0; nt < 8; nt++)
                #pragma unroll
                for (int q = 0; q < 4; q++) s[nt][q] = 0.f;

            #pragma unroll
            for (int kb = 0; kb < 8; kb++) {
                const uint32_t* abase = &Qs[(wid * 16 + gr) * QPAD + kb * 8 + gc];
                uint32_t a0 = abase[0], a1 = abase[8 * QPAD];
                uint32_t a2 = abase[4], a3 = abase[8 * QPAD + 4];
                #pragma unroll
                for (int nt = 0; nt < 8; nt++) {
                    const uint32_t* bbase = &Ks[(nt * 8 + gr) * QPAD + kb * 8 + gc];
                    uint32_t b0 = bbase[0], b1 = bbase[4];
                    asm volatile(
                        "mma.sync.aligned.m16n8k8.row.col.f32.tf32.tf32.f32 "
                        "{%0,%1,%2,%3}, {%4,%5,%6,%7}, {%8,%9}, {%0,%1,%2,%3};"
                        : "+f"(s[nt][0]), "+f"(s[nt][1]), "+f"(s[nt][2]), "+f"(s[nt][3])
                        : "r"(a0), "r"(a1), "r"(a2), "r"(a3), "r"(b0), "r"(b1));
                }
            }

            // ---- scale + causal mask ----
            if (j * KT + KT - 1 <= wrow0) {
                #pragma unroll
                for (int nt = 0; nt < 8; nt++)
                    #pragma unroll
                    for (int q = 0; q < 4; q++) s[nt][q] *= scale;
            } else {
                const int r0g = wrow0 + gr, r1g = wrow0 + gr + 8;
                #pragma unroll
                for (int nt = 0; nt < 8; nt++) {
                    int c0g = j * KT + nt * 8 + 2 * gc;
                    s[nt][0] = (c0g     <= r0g) ? s[nt][0] * scale : -INFINITY;
                    s[nt][1] = (c0g + 1 <= r0g) ? s[nt][1] * scale : -INFINITY;
                    s[nt][2] = (c0g     <= r1g) ? s[nt][2] * scale : -INFINITY;
                    s[nt][3] = (c0g + 1 <= r1g) ? s[nt][3] * scale : -INFINITY;
                }
            }

            // ---- online softmax ----
            #pragma unroll
            for (int half = 0; half < 2; half++) {
                float tmax = -INFINITY;
                #pragma unroll
                for (int nt = 0; nt < 8; nt++)
                    tmax = fmaxf(tmax, fmaxf(s[nt][2 * half], s[nt][2 * half + 1]));
                tmax = fmaxf(tmax, __shfl_xor_sync(0xffffffffu, tmax, 1));
                tmax = fmaxf(tmax, __shfl_xor_sync(0xffffffffu, tmax, 2));
                float mnew  = fmaxf(mrow[half], tmax);
                float alpha = __expf(mrow[half] - mnew);
                float sum = 0.f;
                const int prow = (wid * 16 + gr + 8 * half) * QPAD;
                #pragma unroll
                for (int nt = 0; nt < 8; nt++) {
                    float p0 = __expf(s[nt][2 * half]     - mnew);
                    float p1 = __expf(s[nt][2 * half + 1] - mnew);
                    sum += p0 + p1;
                    Ps[prow + nt * 8 + 2 * gc]     = f2tf32(p0);
                    Ps[prow + nt * 8 + 2 * gc + 1] = f2tf32(p1);
                }
                sum += __shfl_xor_sync(0xffffffffu, sum, 1);
                sum += __shfl_xor_sync(0xffffffffu, sum, 2);
                lrow[half] = lrow[half] * alpha + sum;
                mrow[half] = mnew;
                #pragma unroll
                for (int nt = 0; nt < 8; nt++) {
                    accO[nt][2 * half]     *= alpha;
                    accO[nt][2 * half + 1] *= alpha;
                }
            }
            __syncwarp();

            // ---- O += P @ V ----
            #pragma unroll
            for (int kb = 0; kb < 8; kb++) {
                const uint32_t* abase = &Ps[(wid * 16 + gr) * QPAD + kb * 8 + gc];
                uint32_t a0 = abase[0], a1 = abase[8 * QPAD];
                uint32_t a2 = abase[4], a3 = abase[8 * QPAD + 4];
                #pragma unroll
                for (int nt = 0; nt < 8; nt++) {
                    uint32_t b0 = Vs[(kb * 8 + gc) * QPAD + nt * 8 + gr];
                    uint32_t b1 = Vs[(kb * 8 + gc + 4) * QPAD + nt * 8 + gr];
                    asm volatile(
                        "mma.sync.aligned.m16n8k8.row.col.f32.tf32.tf32.f32 "
                        "{%0,%1,%2,%3}, {%4,%5,%6,%7}, {%8,%9}, {%0,%1,%2,%3};"
                        : "+f"(accO[nt][0]), "+f"(accO[nt][1]),
                          "+f"(accO[nt][2]), "+f"(accO[nt][3])
                        : "r"(a0), "r"(a1), "r"(a2), "r"(a3), "r"(b0), "r"(b1));
                }
            }
        }

        if (j + 1 < nkv) {
            __syncthreads();   // all reads of Ks/Vs for tile j done
            #pragma unroll
            for (int p = 0; p < 4; p++) {
                int idx = tid + p * 256;
                int r = idx >> 4, c = (idx & 15) * 4;
                uint32_t* dk = &Ks[r * QPAD + c];
                dk[0] = f2tf32(kpre[p].x); dk[1] = f2tf32(kpre[p].y);
                dk[2] = f2tf32(kpre[p].z); dk[3] = f2tf32(kpre[p].w);
                uint32_t* dv = &Vs[r * QPAD + c];
                dv[0] = f2tf32(vpre[p].x); dv[1] = f2tf32(vpre[p].y);
                dv[2] = f2tf32(vpre[p].z); dv[3] = f2tf32(vpre[p].w);
            }
            __syncthreads();   // tile j+1 visible
        }
    }

    // ---- epilogue: normalize, write [b, n, h*d] ----
    float inv0 = 1.f / lrow[0];
    float inv1 = 1.f / lrow[1];
    size_t r0 = (size_t)(b * NTOK + wrow0 + gr) * DMODEL + h * DH;
    size_t r1 = r0 + 8 * DMODEL;
    #pragma unroll
    for (int nt = 0; nt < 8; nt++) {
        int c = nt * 8 + 2 * gc;
        *(float2*)&out[r0 + c] = make_float2(accO[nt][0] * inv0, accO[nt][1] * inv0);
        *(float2*)&out[r1 + c] = make_float2(accO[nt][2] * inv1, accO[nt][3] * inv1);
    }
}

// ---------------------------------------------------------------------------
extern "C" void kernel_launch(void* const* d_in, const int* in_sizes, int n_in,
                              void* d_out, int out_size)
{
    const float* x     = (const float*)d_in[0];
    const float* w_qkv = (const float*)d_in[1];
    const float* b_qkv = (const float*)d_in[2];
    const float* w_out = (const float*)d_in[3];
    const float* b_out = (const float*)d_in[4];
    float* out = (float*)d_out;

    float* qkv;  cudaGetSymbolAddress((void**)&qkv, g_qkv);
    float* att;  cudaGetSymbolAddress((void**)&att, g_att);

    const int gemm_smem = (2 * ASTRIDE + 2 * BSTRIDE) * 4;   // 70656 B
    cudaFuncSetAttribute(gemm_tf32_bias,
                         cudaFuncAttributeMaxDynamicSharedMemorySize, gemm_smem);

    // 1) QKV projection (tf32 tensor cores, 2-stage pipeline)
    {
        dim3 grid(QKVCOLS / 128, MROWS / 128);
        gemm_tf32_bias<<<grid, 256, gemm_smem>>>(x, w_qkv, b_qkv, qkv,
                                                 MROWS, QKVCOLS, DMODEL);
    }

    // 2) causal flash attention (tf32 tensor cores, reg-prefetched KV)
    {
        const int smem = (QT * QPAD + 2 * KT * QPAD + QT * QPAD) * 4; // 104448 B
        cudaFuncSetAttribute(attn_tf32,
                             cudaFuncAttributeMaxDynamicSharedMemorySize, smem);
        dim3 grid(BB * NH, NTOK / QT);    // (64, 16)
        attn_tf32<<<grid, 256, smem>>>(qkv, att);
    }

    // 3) output projection (tf32 tensor cores, 2-stage pipeline)
    {
        dim3 grid(DMODEL / 128, MROWS / 128);
        gemm_tf32_bias<<<grid, 256, gemm_smem>>>(att, w_out, b_out, out,
                                                 MROWS, DMODEL, DMODEL);
    }
}